// round 8
// baseline (speedup 1.0000x reference)
#include <cuda_runtime.h>
#include <cuda_bf16.h>

#define NN 512
#define BATCH 32
#define TT 4
#define NROWS (BATCH * TT)                        // 128
#define SRC_ELEMS ((size_t)BATCH * 2 * NN * NN)   // 16,777,216
#define TGT_ELEMS ((size_t)NROWS * NN)            // 65,536

// FFT results, SoA. 2 x 256 KB. Allocation-free scratch.
__device__ float g_Yr[NROWS][NN];
__device__ float g_Yi[NROWS][NN];

typedef unsigned long long u64;

// ---- packed f32x2 helpers ----
__device__ __forceinline__ u64 pk2(float lo, float hi) {
    u64 r; asm("mov.b64 %0, {%1, %2};" : "=l"(r) : "f"(lo), "f"(hi)); return r;
}
__device__ __forceinline__ void up2(u64 v, float& lo, float& hi) {
    asm("mov.b64 {%0, %1}, %2;" : "=f"(lo), "=f"(hi) : "l"(v));
}
__device__ __forceinline__ u64 f2mul(u64 a, u64 b) {
    u64 d; asm("mul.rn.f32x2 %0, %1, %2;" : "=l"(d) : "l"(a), "l"(b)); return d;
}
__device__ __forceinline__ u64 f2fma(u64 a, u64 b, u64 c) {
    u64 d; asm("fma.rn.f32x2 %0, %1, %2, %3;" : "=l"(d) : "l"(a), "l"(b), "l"(c)); return d;
}

// ---------------------------------------------------------------------------
// Kernel 1: 512-pt DFT of real input, per row (b,t).
// 1024 threads: k = tid&255 (Hermitian half), quarter = tid>>8 owns 64 n's.
// Two interleaved rotation chains (even/odd n, step 2*theta_k) -> chain depth
// 16 per resync chunk. Exact sincosf resync every 32 n. smem combine.
// ---------------------------------------------------------------------------
__global__ __launch_bounds__(1024) void dft512_kernel(const float* __restrict__ x) {
    __shared__ float xs[NN];
    __shared__ float s[NN / 2];     // s[1..255]
    __shared__ float d[NN / 2];
    __shared__ float pRe[3][256];
    __shared__ float pIm[3][256];
    __shared__ float pAlt[4];

    const int row = blockIdx.x;     // 0..127
    const int tid = threadIdx.x;    // 0..1023
    const int k   = tid & 255;
    const int q   = tid >> 8;       // 0..3

    if (tid < NN) xs[tid] = x[row * NN + tid];
    __syncthreads();
    if (tid >= 1 && tid < 256) {
        s[tid] = xs[tid] + xs[NN - tid];
        d[tid] = xs[tid] - xs[NN - tid];
    }
    __syncthreads();

    const float W = 6.283185307179586f / (float)NN;
    float s2, c2;
    sincosf(2.0f * W * (float)k, &s2, &c2);   // stride-2 rotation step

    float re = 0.0f, im = 0.0f, alt = 0.0f;

#pragma unroll
    for (int c = 0; c < 2; ++c) {
        const int n0  = q * 64 + c * 32;
        const int phA = (k * n0) & (NN - 1);
        const int phB = (k * (n0 + 1)) & (NN - 1);
        float sA, cA, sB, cB;
        sincosf(W * (float)phA, &sA, &cA);
        sincosf(W * (float)phB, &sB, &cB);
#pragma unroll
        for (int j = 0; j < 16; ++j) {
            const int nA = n0 + 2 * j;      // even n
            const int nB = nA + 1;          // odd n
            if (nA >= 1) {                  // excludes only n==0
                re  = fmaf(s[nA], cA, re);
                im  = fmaf(-d[nA], sA, im);
                alt += s[nA];               // (-1)^even = +
            }
            re  = fmaf(s[nB], cB, re);
            im  = fmaf(-d[nB], sB, im);
            alt -= s[nB];                   // (-1)^odd = -
            const float nrA = fmaf(cA, c2, -(sA * s2));
            sA = fmaf(cA, s2, sA * c2); cA = nrA;
            const float nrB = fmaf(cB, c2, -(sB * s2));
            sB = fmaf(cB, s2, sB * c2); cB = nrB;
        }
    }

    if (q > 0) {
        pRe[q - 1][k] = re;
        pIm[q - 1][k] = im;
        if (k == 0) pAlt[q] = alt;
    } else if (k == 0) {
        pAlt[0] = alt;
    }
    __syncthreads();

    if (q == 0) {
        re += pRe[0][k] + pRe[1][k] + pRe[2][k];
        im += pIm[0][k] + pIm[1][k] + pIm[2][k];
        const float x0 = xs[0], x256 = xs[NN / 2];
        re += x0 + ((k & 1) ? -x256 : x256);
        g_Yr[row][k] = re;
        g_Yi[row][k] = im;
        if (k == 0) {
            g_Yr[row][NN / 2] = x0 + x256 + pAlt[0] + pAlt[1] + pAlt[2] + pAlt[3];
            g_Yi[row][NN / 2] = 0.0f;
        } else {
            g_Yr[row][NN - k] = re;     // conj mirror (real input)
            g_Yi[row][NN - k] = -im;
        }
    }
}

// ---------------------------------------------------------------------------
// Kernel 2: Bx[k,l] = y[k]*conj(y[l])*y[(l-k) mod N], averaged over T.
// Block: 256 thr = 2 k-groups x 128 lanes; thread tile 4k x 4l.
// y[k] broadcasts come from pre-duplicated float2 tables (uniform LDS.64,
// pre-scaled by 0.25) -> no packing MOVs, no epilogue scaling.
// ---------------------------------------------------------------------------
__global__ __launch_bounds__(256, 2) void bispec_kernel(float* __restrict__ out) {
    __shared__ float ysr[TT][NN];
    __shared__ float ysi[TT][NN];
    __shared__ float2 dupr[TT][8];    // ( 0.25*yr,  0.25*yr)
    __shared__ float2 dupi[TT][8];    // ( 0.25*yi,  0.25*yi)
    __shared__ float2 dupnr[TT][8];   // (-0.25*yr, -0.25*yr)

    const int b    = blockIdx.y;      // 0..31
    const int kblk = blockIdx.x;      // 0..63

    {
        const float4* srcr = (const float4*)g_Yr[b * TT];
        const float4* srci = (const float4*)g_Yi[b * TT];
        float4* dr = (float4*)&ysr[0][0];
        float4* di = (float4*)&ysi[0][0];
        for (int i = threadIdx.x; i < TT * NN / 4; i += 256) {
            dr[i] = srcr[i];
            di[i] = srci[i];
        }
    }
    if (threadIdx.x < TT * 8) {
        const int t  = threadIdx.x >> 3;
        const int kl = threadIdx.x & 7;
        const float a = 0.25f * g_Yr[b * TT + t][kblk * 8 + kl];
        const float c = 0.25f * g_Yi[b * TT + t][kblk * 8 + kl];
        dupr[t][kl]  = make_float2(a, a);
        dupi[t][kl]  = make_float2(c, c);
        dupnr[t][kl] = make_float2(-a, -a);
    }
    __syncthreads();

    const int lane  = threadIdx.x & 127;
    const int ksub  = threadIdx.x >> 7;     // warp-uniform
    const int k0    = kblk * 8 + ksub * 4;
    const int kb    = ksub * 4;
    const int lbase = lane * 4;

    u64 accr[4][2], acci[4][2];
#pragma unroll
    for (int a = 0; a < 4; ++a)
#pragma unroll
        for (int p = 0; p < 2; ++p) { accr[a][p] = 0ull; acci[a][p] = 0ull; }

#pragma unroll
    for (int t = 0; t < TT; ++t) {
        // y[l]: warp-contiguous float4 (conflict-free)
        const float4 lr = *(const float4*)&ysr[t][lbase];
        const float4 li = *(const float4*)&ysi[t][lbase];
        const u64 ylr2[2] = { pk2(lr.x, lr.y), pk2(lr.z, lr.w) };
        const u64 yli2[2] = { pk2(li.x, li.y), pk2(li.z, li.w) };

        // yc window: 8 consecutive values [lbase-k0-4 .. lbase-k0+3]
        const int base  = (lbase - k0 - 4 + 1024) & (NN - 1);
        const int base2 = (base + 4) & (NN - 1);
        const float4 c0r = *(const float4*)&ysr[t][base];
        const float4 c1r = *(const float4*)&ysr[t][base2];
        const float4 c0i = *(const float4*)&ysi[t][base];
        const float4 c1i = *(const float4*)&ysi[t][base2];
        const float wr[8] = {c0r.x, c0r.y, c0r.z, c0r.w, c1r.x, c1r.y, c1r.z, c1r.w};
        const float wi[8] = {c0i.x, c0i.y, c0i.z, c0i.w, c1i.x, c1i.y, c1i.z, c1i.w};
        const u64 cre[4] = { pk2(wr[0],wr[1]), pk2(wr[2],wr[3]), pk2(wr[4],wr[5]), pk2(wr[6],wr[7]) };
        const u64 cie[4] = { pk2(wi[0],wi[1]), pk2(wi[2],wi[3]), pk2(wi[4],wi[5]), pk2(wi[6],wi[7]) };
        const u64 cro[3] = { pk2(wr[1],wr[2]), pk2(wr[3],wr[4]), pk2(wr[5],wr[6]) };
        const u64 cio[3] = { pk2(wi[1],wi[2]), pk2(wi[3],wi[4]), pk2(wi[5],wi[6]) };

#pragma unroll
        for (int ka = 0; ka < 4; ++ka) {
            // broadcast packs: uniform-address LDS.64, pre-scaled by 0.25
            const u64 ykr2  = *(const u64*)&dupr[t][kb + ka];
            const u64 yki2  = *(const u64*)&dupi[t][kb + ka];
            const u64 nykr2 = *(const u64*)&dupnr[t][kb + ka];
#pragma unroll
            for (int lp = 0; lp < 2; ++lp) {
                const int j0 = 4 + 2 * lp - ka;        // 1..6, compile-time
                const u64 ycr2 = (ka & 1) ? cro[(j0 - 1) >> 1] : cre[j0 >> 1];
                const u64 yci2 = (ka & 1) ? cio[(j0 - 1) >> 1] : cie[j0 >> 1];
                // a = (0.25*y[k]) * conj(y[l])
                const u64 ar2  = f2fma(yki2, yli2[lp], f2mul(ykr2, ylr2[lp]));
                const u64 ai2  = f2fma(nykr2, yli2[lp], f2mul(yki2, ylr2[lp]));
                const u64 nai2 = ai2 ^ 0x8000000080000000ULL;
                // Bx = a * yc
                accr[ka][lp] = f2fma(ar2,  ycr2, accr[ka][lp]);
                accr[ka][lp] = f2fma(nai2, yci2, accr[ka][lp]);
                acci[ka][lp] = f2fma(ar2,  yci2, acci[ka][lp]);
                acci[ka][lp] = f2fma(ai2,  ycr2, acci[ka][lp]);
            }
        }
    }

    float* outb = out + (size_t)b * 2 * NN * NN;
#pragma unroll
    for (int ka = 0; ka < 4; ++ka) {
        const int k = k0 + ka;
        float r0, r1, r2, r3, i0, i1, i2, i3;
        up2(accr[ka][0], r0, r1);
        up2(accr[ka][1], r2, r3);
        up2(acci[ka][0], i0, i1);
        up2(acci[ka][1], i2, i3);
        *(float4*)&outb[(size_t)k * NN + lbase] = make_float4(r0, r1, r2, r3);
        *(float4*)&outb[(size_t)NN * NN + (size_t)k * NN + lbase] = make_float4(i0, i1, i2, i3);
    }
}

extern "C" void kernel_launch(void* const* d_in, const int* in_sizes, int n_in,
                              void* d_out, int out_size) {
    const float* target = (const float*)d_in[0];
    float* out = (float*)d_out;

    dft512_kernel<<<NROWS, 1024>>>(target);

    dim3 grid(NN / 8, BATCH);
    bispec_kernel<<<grid, 256>>>(out);

    if ((size_t)out_size >= SRC_ELEMS + TGT_ELEMS) {
        cudaMemcpyAsync(out + SRC_ELEMS, target, TGT_ELEMS * sizeof(float),
                        cudaMemcpyDeviceToDevice, 0);
    }
}